// round 6
// baseline (speedup 1.0000x reference)
#include <cuda_runtime.h>
#include <cuda_bf16.h>
#include <cstdint>
#include <math.h>

#define BATCH 8
#define NQ    1024
#define NKV   4096
#define DIM   512

// ---------------- scratch (device globals: allocation-free) ----------------
// split bf16 hi/lo operand arrays
__device__ __align__(16) __nv_bfloat16 s_ph [BATCH*NQ*DIM],  s_pl [BATCH*NQ*DIM];   // prototype
__device__ __align__(16) __nv_bfloat16 s_xh [BATCH*NKV*DIM], s_xl [BATCH*NKV*DIM];  // q_x
__device__ __align__(16) __nv_bfloat16 s_wqh[DIM*DIM], s_wql[DIM*DIM];
__device__ __align__(16) __nv_bfloat16 s_wkh[DIM*DIM], s_wkl[DIM*DIM];
__device__ __align__(16) __nv_bfloat16 s_wvh[DIM*DIM], s_wvl[DIM*DIM];
__device__ __align__(16) __nv_bfloat16 s_wph[DIM*DIM], s_wpl[DIM*DIM];
__device__ __align__(16) __nv_bfloat16 s_qh [BATCH*NQ*DIM],  s_ql [BATCH*NQ*DIM];   // q
__device__ __align__(16) __nv_bfloat16 s_kh [BATCH*NKV*DIM], s_kl [BATCH*NKV*DIM];  // k
__device__ __align__(16) __nv_bfloat16 s_vth[BATCH*DIM*NKV], s_vtl[BATCH*DIM*NKV];  // vT
__device__ __align__(16) __nv_bfloat16 s_aph[(size_t)BATCH*NQ*NKV];                 // softmax probs hi
__device__ __align__(16) __nv_bfloat16 s_apl[(size_t)BATCH*NQ*NKV];                 // softmax probs lo
__device__ __align__(16) __nv_bfloat16 s_oh [BATCH*NQ*DIM],  s_ol [BATCH*NQ*DIM];   // x (pre-proj)
__device__ __align__(16) float g_attn[(size_t)BATCH*NQ*NKV];                        // fp32 scores

// ============================================================================
// helpers
// ============================================================================
__device__ __forceinline__ uint32_t smem_u32(const void* p) {
    uint32_t a;
    asm("{ .reg .u64 t; cvta.to.shared.u64 t, %1; cvt.u32.u64 %0, t; }"
        : "=r"(a) : "l"(p));
    return a;
}
__device__ __forceinline__ void cp_async16(uint32_t saddr, const void* gaddr) {
    asm volatile("cp.async.ca.shared.global [%0], [%1], 16;"
                 :: "r"(saddr), "l"(gaddr) : "memory");
}
__device__ __forceinline__ void cp_commit() {
    asm volatile("cp.async.commit_group;" ::: "memory");
}
__device__ __forceinline__ void cp_wait1() {
    asm volatile("cp.async.wait_group 1;" ::: "memory");
}
__device__ __forceinline__ void cp_wait0() {
    asm volatile("cp.async.wait_group 0;" ::: "memory");
}

// mma.sync m16n8k16 bf16: d += a*b (f32 accumulators in-place)
__device__ __forceinline__ void mma_bf16(float* d, const uint32_t* a, const uint32_t* b) {
    asm volatile(
        "mma.sync.aligned.m16n8k16.row.col.f32.bf16.bf16.f32 "
        "{%0,%1,%2,%3}, {%4,%5,%6,%7}, {%8,%9}, {%0,%1,%2,%3};"
        : "+f"(d[0]), "+f"(d[1]), "+f"(d[2]), "+f"(d[3])
        : "r"(a[0]), "r"(a[1]), "r"(a[2]), "r"(a[3]), "r"(b[0]), "r"(b[1]));
}

// split (x,y) -> packed bf16x2 hi (x in low 16) + packed bf16x2 lo residuals
__device__ __forceinline__ void pack_split(float x, float y, uint32_t& h, uint32_t& l) {
    asm("cvt.rn.bf16x2.f32 %0, %1, %2;" : "=r"(h) : "f"(y), "f"(x));
    float h0 = __uint_as_float(h << 16);
    float h1 = __uint_as_float(h & 0xFFFF0000u);
    asm("cvt.rn.bf16x2.f32 %0, %1, %2;" : "=r"(l) : "f"(y - h1), "f"(x - h0));
}

// ============================================================================
// elementwise fp32 -> (hi, lo) bf16 split, 4 floats per thread
// ============================================================================
__global__ void __launch_bounds__(256) split_kernel(
    const float* __restrict__ in, __nv_bfloat16* __restrict__ h,
    __nv_bfloat16* __restrict__ l, int n4)
{
    int i = blockIdx.x * 256 + threadIdx.x;
    if (i >= n4) return;
    float4 v = ((const float4*)in)[i];
    uint32_t h0, l0, h1, l1;
    pack_split(v.x, v.y, h0, l0);
    pack_split(v.z, v.w, h1, l1);
    ((uint2*)h)[i] = make_uint2(h0, h1);
    ((uint2*)l)[i] = make_uint2(l0, l1);
}

// ============================================================================
// bf16x3 GEMM NT on pre-split operands:
//   C[M,N] = alpha * (Ah+Al)[M,K] @ (Bh+Bl)[N,K]^T   (lo*lo dropped)
// Output: fp32 (Cf) OR split bf16 (Ch, Cl).
// CTA tile 128x128, K-tile 32 (2 x k16), 2-stage cp.async, 256 threads
// (8 warps 2x4, warp tile 64x32). SMEM rows = 40 bf16 (80B): 20-bank row
// stride makes all fragment LDS.32 patterns hit 32 distinct banks.
// blockIdx.z = batch; sA/sB/sC per-batch element strides (0 = broadcast).
// M,N % 128 == 0, K % 32 == 0.
// ============================================================================
#define PAD2      40                       // bf16 per smem row
#define TILE_B    (128 * PAD2 * 2)         // bytes per tile (10240)
#define STAGE_B   (4 * TILE_B)             // Ah, Al, Bh, Bl (40960)
#define GEMM_SMEM (2 * STAGE_B)            // 81920

__global__ void __launch_bounds__(256, 2) gemm_nt_split(
    const __nv_bfloat16* __restrict__ Ah, const __nv_bfloat16* __restrict__ Al,
    const __nv_bfloat16* __restrict__ Bh, const __nv_bfloat16* __restrict__ Bl,
    float* __restrict__ Cf,
    __nv_bfloat16* __restrict__ Ch, __nv_bfloat16* __restrict__ Cl,
    int M, int N, int K, size_t sA, size_t sB, size_t sC, float alpha)
{
    extern __shared__ __align__(16) char smem[];
    const uint32_t sbase = smem_u32(smem);

    const int t    = threadIdx.x;
    const int wid  = t >> 5;
    const int lane = t & 31;
    const int g    = lane >> 2;
    const int c    = lane & 3;
    const int warp_m = wid >> 2;    // 0..1
    const int warp_n = wid & 3;     // 0..3

    Ah += (size_t)blockIdx.z * sA;  Al += (size_t)blockIdx.z * sA;
    Bh += (size_t)blockIdx.z * sB;  Bl += (size_t)blockIdx.z * sB;
    const int m0 = blockIdx.y * 128;
    const int n0 = blockIdx.x * 128;

    // ---- async load of one K-tile (32 bf16 wide) for all 4 arrays ----
    auto load_tile = [&](int kt, int s) {
        const uint32_t st = sbase + (uint32_t)(s * STAGE_B);
        const int kb = kt * 32;
        #pragma unroll
        for (int ph = 0; ph < 2; ph++) {
            int idx = ph * 256 + t;          // 0..511
            int row = idx >> 2;              // 0..127
            int c4  = idx & 3;               // 16B chunk (8 bf16)
            uint32_t so = (uint32_t)(row * (PAD2 * 2) + c4 * 16);
            const size_t ga = (size_t)(m0 + row) * K + kb + c4 * 8;
            const size_t gb = (size_t)(n0 + row) * K + kb + c4 * 8;
            cp_async16(st + 0 * TILE_B + so, Ah + ga);
            cp_async16(st + 1 * TILE_B + so, Al + ga);
            cp_async16(st + 2 * TILE_B + so, Bh + gb);
            cp_async16(st + 3 * TILE_B + so, Bl + gb);
        }
        cp_commit();
    };

    float acc[4][4][4] = {};   // [mtile][ntile][reg]

    const int nkt = K >> 5;
    load_tile(0, 0);

    for (int kt = 0; kt < nkt; kt++) {
        const int s = kt & 1;
        if (kt + 1 < nkt) {
            load_tile(kt + 1, s ^ 1);
            cp_wait1();
        } else {
            cp_wait0();
        }
        __syncthreads();

        const char* pAh = smem + s * STAGE_B + 0 * TILE_B + warp_m * 64 * (PAD2 * 2);
        const char* pBh = smem + s * STAGE_B + 2 * TILE_B + warp_n * 32 * (PAD2 * 2);

        #pragma unroll
        for (int ks2 = 0; ks2 < 2; ks2++) {
            const int kcb = ks2 * 32 + c * 4;     // byte offset of k-pair in row

            // B fragments for all 4 n-tiles
            uint32_t bh[4][2], bl[4][2];
            #pragma unroll
            for (int nt = 0; nt < 4; nt++) {
                const int rb = (nt * 8 + g) * (PAD2 * 2);
                bh[nt][0] = *(const uint32_t*)(pBh + rb + kcb);
                bh[nt][1] = *(const uint32_t*)(pBh + rb + kcb + 16);
                bl[nt][0] = *(const uint32_t*)(pBh + TILE_B + rb + kcb);
                bl[nt][1] = *(const uint32_t*)(pBh + TILE_B + rb + kcb + 16);
            }

            #pragma unroll
            for (int mt = 0; mt < 4; mt++) {
                const int r0 = (mt * 16 + g) * (PAD2 * 2);
                const int r1 = r0 + 8 * (PAD2 * 2);
                uint32_t ah[4], al[4];
                ah[0] = *(const uint32_t*)(pAh + r0 + kcb);
                ah[1] = *(const uint32_t*)(pAh + r1 + kcb);
                ah[2] = *(const uint32_t*)(pAh + r0 + kcb + 16);
                ah[3] = *(const uint32_t*)(pAh + r1 + kcb + 16);
                al[0] = *(const uint32_t*)(pAh + TILE_B + r0 + kcb);
                al[1] = *(const uint32_t*)(pAh + TILE_B + r1 + kcb);
                al[2] = *(const uint32_t*)(pAh + TILE_B + r0 + kcb + 16);
                al[3] = *(const uint32_t*)(pAh + TILE_B + r1 + kcb + 16);
                #pragma unroll
                for (int nt = 0; nt < 4; nt++) {
                    mma_bf16(acc[mt][nt], al, bh[nt]);   // small terms first
                    mma_bf16(acc[mt][nt], ah, bl[nt]);
                    mma_bf16(acc[mt][nt], ah, bh[nt]);
                }
            }
        }
        __syncthreads();
    }

    // ---- epilogue ----
    if (Cf) {
        Cf += (size_t)blockIdx.z * sC;
        #pragma unroll
        for (int mt = 0; mt < 4; mt++) {
            const int row = m0 + warp_m * 64 + mt * 16 + g;
            #pragma unroll
            for (int nt = 0; nt < 4; nt++) {
                const int col = n0 + warp_n * 32 + nt * 8 + 2 * c;
                *(float2*)(Cf + (size_t)row * N + col) =
                    make_float2(acc[mt][nt][0] * alpha, acc[mt][nt][1] * alpha);
                *(float2*)(Cf + (size_t)(row + 8) * N + col) =
                    make_float2(acc[mt][nt][2] * alpha, acc[mt][nt][3] * alpha);
            }
        }
    } else {
        Ch += (size_t)blockIdx.z * sC;
        Cl += (size_t)blockIdx.z * sC;
        #pragma unroll
        for (int mt = 0; mt < 4; mt++) {
            const int row = m0 + warp_m * 64 + mt * 16 + g;
            #pragma unroll
            for (int nt = 0; nt < 4; nt++) {
                const int col = n0 + warp_n * 32 + nt * 8 + 2 * c;
                uint32_t h, l;
                pack_split(acc[mt][nt][0] * alpha, acc[mt][nt][1] * alpha, h, l);
                *(uint32_t*)(Ch + (size_t)row * N + col) = h;
                *(uint32_t*)(Cl + (size_t)row * N + col) = l;
                pack_split(acc[mt][nt][2] * alpha, acc[mt][nt][3] * alpha, h, l);
                *(uint32_t*)(Ch + (size_t)(row + 8) * N + col) = h;
                *(uint32_t*)(Cl + (size_t)(row + 8) * N + col) = l;
            }
        }
    }
}

// ============================================================================
// Masked softmax over rows of attn [BATCH*NQ, NKV] -> split bf16 probs.
// mask int32 [B, NKV]; bias -10000 exactly as reference.
// ============================================================================
__global__ void __launch_bounds__(256) softmax_split_kernel(
    const float* __restrict__ attn, const int* __restrict__ mask,
    __nv_bfloat16* __restrict__ Ph, __nv_bfloat16* __restrict__ Pl)
{
    const int row = blockIdx.x;
    const int b   = row >> 10;             // NQ = 1024
    const float2* p = (const float2*)(attn + (size_t)row * NKV);
    const int2* mrow = (const int2*)(mask + b * NKV);

    float2 v[8];
    float mx = -3.0e38f;
    #pragma unroll
    for (int i = 0; i < 8; i++) {
        int m2 = threadIdx.x + i * 256;
        float2 x = p[m2];
        int2 mm = mrow[m2];
        x.x += mm.x ? 0.0f : -10000.0f;
        x.y += mm.y ? 0.0f : -10000.0f;
        v[i] = x;
        mx = fmaxf(mx, fmaxf(x.x, x.y));
    }

    __shared__ float red[8];
    #pragma unroll
    for (int o = 16; o; o >>= 1) mx = fmaxf(mx, __shfl_xor_sync(0xffffffffu, mx, o));
    if ((threadIdx.x & 31) == 0) red[threadIdx.x >> 5] = mx;
    __syncthreads();
    float bm = red[0];
    #pragma unroll
    for (int w = 1; w < 8; w++) bm = fmaxf(bm, red[w]);
    __syncthreads();

    float sum = 0.0f;
    #pragma unroll
    for (int i = 0; i < 8; i++) {
        v[i].x = __expf(v[i].x - bm);
        v[i].y = __expf(v[i].y - bm);
        sum += v[i].x + v[i].y;
    }
    #pragma unroll
    for (int o = 16; o; o >>= 1) sum += __shfl_xor_sync(0xffffffffu, sum, o);
    if ((threadIdx.x & 31) == 0) red[threadIdx.x >> 5] = sum;
    __syncthreads();
    float ts = red[0];
    #pragma unroll
    for (int w = 1; w < 8; w++) ts += red[w];
    float inv = 1.0f / ts;

    #pragma unroll
    for (int i = 0; i < 8; i++) {
        int m2 = threadIdx.x + i * 256;
        uint32_t h, l;
        pack_split(v[i].x * inv, v[i].y * inv, h, l);
        *(uint32_t*)(Ph + (size_t)row * NKV + 2 * m2) = h;
        *(uint32_t*)(Pl + (size_t)row * NKV + 2 * m2) = l;
    }
}

// ============================================================================
// launch
// ============================================================================
extern "C" void kernel_launch(void* const* d_in, const int* in_sizes, int n_in,
                              void* d_out, int out_size)
{
    const float* prototype = (const float*)d_in[0];   // [B, NQ, DIM]
    const float* q_x       = (const float*)d_in[1];   // [B, NKV, DIM]
    const int*   mask      = (const int*)  d_in[2];   // [B, NKV]
    const float* Wq        = (const float*)d_in[3];
    const float* Wk        = (const float*)d_in[4];
    const float* Wv        = (const float*)d_in[5];
    const float* Wproj     = (const float*)d_in[6];
    float* out = (float*)d_out;                        // [B, NQ, DIM] fp32

    __nv_bfloat16 *ph, *pl, *xh, *xl, *wqh, *wql, *wkh, *wkl, *wvh, *wvl,
                  *wph, *wpl, *qh, *ql, *kh, *kl, *vth, *vtl, *aph, *apl, *oh, *ol;
    float* attn;
    cudaGetSymbolAddress((void**)&ph,  s_ph);  cudaGetSymbolAddress((void**)&pl,  s_pl);
    cudaGetSymbolAddress((void**)&xh,  s_xh);  cudaGetSymbolAddress((void**)&xl,  s_xl);
    cudaGetSymbolAddress((void**)&wqh, s_wqh); cudaGetSymbolAddress((void**)&wql, s_wql);
    cudaGetSymbolAddress((void**)&wkh, s_wkh); cudaGetSymbolAddress((void**)&wkl, s_wkl);
    cudaGetSymbolAddress((void**)&wvh, s_wvh); cudaGetSymbolAddress((void**)&wvl, s_wvl);
    cudaGetSymbolAddress((void**)&wph, s_wph); cudaGetSymbolAddress((void**)&wpl, s_wpl);
    cudaGetSymbolAddress((void**)&qh,  s_qh);  cudaGetSymbolAddress((void**)&ql,  s_ql);
    cudaGetSymbolAddress((void**)&kh,  s_kh);  cudaGetSymbolAddress((void**)&kl,  s_kl);
    cudaGetSymbolAddress((void**)&vth, s_vth); cudaGetSymbolAddress((void**)&vtl, s_vtl);
    cudaGetSymbolAddress((void**)&aph, s_aph); cudaGetSymbolAddress((void**)&apl, s_apl);
    cudaGetSymbolAddress((void**)&oh,  s_oh);  cudaGetSymbolAddress((void**)&ol,  s_ol);
    cudaGetSymbolAddress((void**)&attn, g_attn);

    cudaFuncSetAttribute(gemm_nt_split,
                         cudaFuncAttributeMaxDynamicSharedMemorySize, GEMM_SMEM);

    const float scale = 0.04419417382415922f;  // 1/sqrt(512)
    dim3 blk(256);

    // ---- split external inputs ----
    split_kernel<<<(BATCH*NQ*DIM/4 + 255)/256, blk>>>(prototype, ph, pl, BATCH*NQ*DIM/4);
    split_kernel<<<(BATCH*NKV*DIM/4 + 255)/256, blk>>>(q_x, xh, xl, BATCH*NKV*DIM/4);
    split_kernel<<<(DIM*DIM/4 + 255)/256, blk>>>(Wq, wqh, wql, DIM*DIM/4);
    split_kernel<<<(DIM*DIM/4 + 255)/256, blk>>>(Wk, wkh, wkl, DIM*DIM/4);
    split_kernel<<<(DIM*DIM/4 + 255)/256, blk>>>(Wv, wvh, wvl, DIM*DIM/4);
    split_kernel<<<(DIM*DIM/4 + 255)/256, blk>>>(Wproj, wph, wpl, DIM*DIM/4);

    // q = prototype @ Wq^T : M=8192, N=512, K=512 -> split
    gemm_nt_split<<<dim3(DIM/128, (BATCH*NQ)/128, 1), blk, GEMM_SMEM>>>(
        ph, pl, wqh, wql, nullptr, qh, ql,
        BATCH*NQ, DIM, DIM, 0, 0, 0, 1.0f);

    // k = q_x @ Wk^T : M=32768, N=512, K=512 -> split
    gemm_nt_split<<<dim3(DIM/128, (BATCH*NKV)/128, 1), blk, GEMM_SMEM>>>(
        xh, xl, wkh, wkl, nullptr, kh, kl,
        BATCH*NKV, DIM, DIM, 0, 0, 0, 1.0f);

    // vT[b] = Wv @ q_x[b]^T : per batch M=512, N=4096, K=512 -> split
    gemm_nt_split<<<dim3(NKV/128, DIM/128, BATCH), blk, GEMM_SMEM>>>(
        wvh, wvl, xh, xl, nullptr, vth, vtl,
        DIM, NKV, DIM, 0, (size_t)NKV*DIM, (size_t)DIM*NKV, 1.0f);

    // attn[b] = scale * q[b] @ k[b]^T : M=1024, N=4096, K=512 -> fp32
    gemm_nt_split<<<dim3(NKV/128, NQ/128, BATCH), blk, GEMM_SMEM>>>(
        qh, ql, kh, kl, attn, nullptr, nullptr,
        NQ, NKV, DIM, (size_t)NQ*DIM, (size_t)NKV*DIM, (size_t)NQ*NKV, scale);

    // masked softmax -> split probs
    softmax_split_kernel<<<BATCH*NQ, blk>>>(attn, mask, aph, apl);

    // x[b] = P[b] @ vT[b]^T : M=1024, N=512, K=4096 -> split
    gemm_nt_split<<<dim3(DIM/128, NQ/128, BATCH), blk, GEMM_SMEM>>>(
        aph, apl, vth, vtl, nullptr, oh, ol,
        NQ, DIM, NKV, (size_t)NQ*NKV, (size_t)DIM*NKV, (size_t)NQ*DIM, 1.0f);

    // out = x @ Wproj^T : M=8192, N=512, K=512 -> fp32
    gemm_nt_split<<<dim3(DIM/128, (BATCH*NQ)/128, 1), blk, GEMM_SMEM>>>(
        oh, ol, wph, wpl, out, nullptr, nullptr,
        BATCH*NQ, DIM, DIM, 0, 0, 0, 1.0f);
}

// round 7
// speedup vs baseline: 1.0545x; 1.0545x over previous
#include <cuda_runtime.h>
#include <cuda_bf16.h>
#include <cstdint>
#include <math.h>

#define BATCH 8
#define NQ    1024
#define NKV   4096
#define DIM   512

// ---------------- scratch (device globals: allocation-free) ----------------
__device__ __align__(16) __nv_bfloat16 s_ph [BATCH*NQ*DIM],  s_pl [BATCH*NQ*DIM];   // prototype
__device__ __align__(16) __nv_bfloat16 s_xh [BATCH*NKV*DIM], s_xl [BATCH*NKV*DIM];  // q_x
__device__ __align__(16) __nv_bfloat16 s_wqh[DIM*DIM], s_wql[DIM*DIM];
__device__ __align__(16) __nv_bfloat16 s_wkh[DIM*DIM], s_wkl[DIM*DIM];
__device__ __align__(16) __nv_bfloat16 s_wvh[DIM*DIM], s_wvl[DIM*DIM];
__device__ __align__(16) __nv_bfloat16 s_wph[DIM*DIM], s_wpl[DIM*DIM];
__device__ __align__(16) __nv_bfloat16 s_qh [BATCH*NQ*DIM],  s_ql [BATCH*NQ*DIM];   // q
__device__ __align__(16) __nv_bfloat16 s_kh [BATCH*NKV*DIM], s_kl [BATCH*NKV*DIM];  // k
__device__ __align__(16) __nv_bfloat16 s_vth[BATCH*DIM*NKV], s_vtl[BATCH*DIM*NKV];  // vT
__device__ __align__(16) __nv_bfloat16 s_aph[(size_t)BATCH*NQ*NKV];                 // probs hi
__device__ __align__(16) __nv_bfloat16 s_apl[(size_t)BATCH*NQ*NKV];                 // probs lo
__device__ __align__(16) __nv_bfloat16 s_oh [BATCH*NQ*DIM],  s_ol [BATCH*NQ*DIM];   // x
__device__ __align__(16) float g_attn[(size_t)BATCH*NQ*NKV];                        // fp32 scores

// ============================================================================
// helpers
// ============================================================================
__device__ __forceinline__ uint32_t smem_u32(const void* p) {
    uint32_t a;
    asm("{ .reg .u64 t; cvta.to.shared.u64 t, %1; cvt.u32.u64 %0, t; }"
        : "=r"(a) : "l"(p));
    return a;
}
__device__ __forceinline__ void cp_async16(uint32_t saddr, const void* gaddr) {
    asm volatile("cp.async.ca.shared.global [%0], [%1], 16;"
                 :: "r"(saddr), "l"(gaddr) : "memory");
}
__device__ __forceinline__ void cp_commit() {
    asm volatile("cp.async.commit_group;" ::: "memory");
}
__device__ __forceinline__ void cp_wait1() {
    asm volatile("cp.async.wait_group 1;" ::: "memory");
}
__device__ __forceinline__ void cp_wait0() {
    asm volatile("cp.async.wait_group 0;" ::: "memory");
}

// mma.sync m16n8k16 bf16: d += a*b (f32 accumulators in-place)
__device__ __forceinline__ void mma_bf16(float* d, const uint32_t* a, const uint32_t* b) {
    asm volatile(
        "mma.sync.aligned.m16n8k16.row.col.f32.bf16.bf16.f32 "
        "{%0,%1,%2,%3}, {%4,%5,%6,%7}, {%8,%9}, {%0,%1,%2,%3};"
        : "+f"(d[0]), "+f"(d[1]), "+f"(d[2]), "+f"(d[3])
        : "r"(a[0]), "r"(a[1]), "r"(a[2]), "r"(a[3]), "r"(b[0]), "r"(b[1]));
}

// split (x,y) -> packed bf16x2 hi (x in low 16) + packed bf16x2 lo residuals
__device__ __forceinline__ void pack_split(float x, float y, uint32_t& h, uint32_t& l) {
    asm("cvt.rn.bf16x2.f32 %0, %1, %2;" : "=r"(h) : "f"(y), "f"(x));
    float h0 = __uint_as_float(h << 16);
    float h1 = __uint_as_float(h & 0xFFFF0000u);
    asm("cvt.rn.bf16x2.f32 %0, %1, %2;" : "=r"(l) : "f"(y - h1), "f"(x - h0));
}

// ============================================================================
// elementwise fp32 -> (hi, lo) bf16 split, 4 floats per thread
// ============================================================================
__global__ void __launch_bounds__(256) split_kernel(
    const float* __restrict__ in, __nv_bfloat16* __restrict__ h,
    __nv_bfloat16* __restrict__ l, int n4)
{
    int i = blockIdx.x * 256 + threadIdx.x;
    if (i >= n4) return;
    float4 v = ((const float4*)in)[i];
    uint32_t h0, l0, h1, l1;
    pack_split(v.x, v.y, h0, l0);
    pack_split(v.z, v.w, h1, l1);
    ((uint2*)h)[i] = make_uint2(h0, h1);
    ((uint2*)l)[i] = make_uint2(l0, l1);
}

// ============================================================================
// bf16x3 GEMM NT on pre-split operands, warp tile 64x64:
//   C[M,N] = alpha * (Ah+Al)[M,K] @ (Bh+Bl)[N,K]^T   (lo*lo dropped)
// CTA tile 128x128, 128 threads (4 warps, 2x2 grid), K-tile 32 (2 x k16),
// 2-stage cp.async. SMEM rows = 40 bf16 (80B, 20-bank stride):
// all fragment LDS.32 patterns hit 32 distinct banks.
// 24.6 MAC/smem-byte (vs 16 for 64x32) -> tensor pipe becomes the limiter.
// Output: fp32 (Cf) OR split bf16 (Ch, Cl).
// blockIdx.z = batch; sA/sB/sC per-batch element strides (0 = broadcast).
// M,N % 128 == 0, K % 32 == 0.
// ============================================================================
#define PAD2      40                       // bf16 per smem row
#define ROW_B     (PAD2 * 2)               // 80 bytes per row
#define TILE_B    (128 * ROW_B)            // bytes per tile (10240)
#define STAGE_B   (4 * TILE_B)             // Ah, Al, Bh, Bl (40960)
#define GEMM_SMEM (2 * STAGE_B)            // 81920

__global__ void __launch_bounds__(128, 2) gemm_nt_split(
    const __nv_bfloat16* __restrict__ Ah, const __nv_bfloat16* __restrict__ Al,
    const __nv_bfloat16* __restrict__ Bh, const __nv_bfloat16* __restrict__ Bl,
    float* __restrict__ Cf,
    __nv_bfloat16* __restrict__ Ch, __nv_bfloat16* __restrict__ Cl,
    int M, int N, int K, size_t sA, size_t sB, size_t sC, float alpha)
{
    extern __shared__ __align__(16) char smem[];
    const uint32_t sbase = smem_u32(smem);

    const int t    = threadIdx.x;
    const int wid  = t >> 5;
    const int lane = t & 31;
    const int g    = lane >> 2;
    const int c    = lane & 3;
    const int warp_m = wid >> 1;    // 0..1
    const int warp_n = wid & 1;     // 0..1

    Ah += (size_t)blockIdx.z * sA;  Al += (size_t)blockIdx.z * sA;
    Bh += (size_t)blockIdx.z * sB;  Bl += (size_t)blockIdx.z * sB;
    const int m0 = blockIdx.y * 128;
    const int n0 = blockIdx.x * 128;

    // ---- async load of one K-tile (32 bf16 wide) for all 4 arrays ----
    auto load_tile = [&](int kt, int s) {
        const uint32_t st = sbase + (uint32_t)(s * STAGE_B);
        const int kb = kt * 32;
        #pragma unroll
        for (int ph = 0; ph < 4; ph++) {
            int idx = ph * 128 + t;          // 0..511
            int row = idx >> 2;              // 0..127
            int c4  = idx & 3;               // 16B chunk (8 bf16)
            uint32_t so = (uint32_t)(row * ROW_B + c4 * 16);
            const size_t ga = (size_t)(m0 + row) * K + kb + c4 * 8;
            const size_t gb = (size_t)(n0 + row) * K + kb + c4 * 8;
            cp_async16(st + 0 * TILE_B + so, Ah + ga);
            cp_async16(st + 1 * TILE_B + so, Al + ga);
            cp_async16(st + 2 * TILE_B + so, Bh + gb);
            cp_async16(st + 3 * TILE_B + so, Bl + gb);
        }
        cp_commit();
    };

    float acc[4][8][4] = {};   // [mtile 16-rows][ntile 8-cols][reg]

    const int nkt = K >> 5;
    load_tile(0, 0);

    for (int kt = 0; kt < nkt; kt++) {
        const int s = kt & 1;
        if (kt + 1 < nkt) {
            load_tile(kt + 1, s ^ 1);
            cp_wait1();
        } else {
            cp_wait0();
        }
        __syncthreads();

        const char* pA = smem + s * STAGE_B + 0 * TILE_B + warp_m * 64 * ROW_B;
        const char* pB = smem + s * STAGE_B + 2 * TILE_B + warp_n * 64 * ROW_B;

        #pragma unroll
        for (int ks2 = 0; ks2 < 2; ks2++) {
            const int kcb = ks2 * 32 + c * 4;     // byte offset of k-pair in row

            // B fragments for all 8 n-tiles (reused across 4 m-tiles)
            uint32_t bh[8][2], bl[8][2];
            #pragma unroll
            for (int nt = 0; nt < 8; nt++) {
                const int rb = (nt * 8 + g) * ROW_B;
                bh[nt][0] = *(const uint32_t*)(pB + rb + kcb);
                bh[nt][1] = *(const uint32_t*)(pB + rb + kcb + 16);
                bl[nt][0] = *(const uint32_t*)(pB + TILE_B + rb + kcb);
                bl[nt][1] = *(const uint32_t*)(pB + TILE_B + rb + kcb + 16);
            }

            #pragma unroll
            for (int mt = 0; mt < 4; mt++) {
                const int r0 = (mt * 16 + g) * ROW_B;
                const int r1 = r0 + 8 * ROW_B;
                uint32_t ah[4], al[4];
                ah[0] = *(const uint32_t*)(pA + r0 + kcb);
                ah[1] = *(const uint32_t*)(pA + r1 + kcb);
                ah[2] = *(const uint32_t*)(pA + r0 + kcb + 16);
                ah[3] = *(const uint32_t*)(pA + r1 + kcb + 16);
                al[0] = *(const uint32_t*)(pA + TILE_B + r0 + kcb);
                al[1] = *(const uint32_t*)(pA + TILE_B + r1 + kcb);
                al[2] = *(const uint32_t*)(pA + TILE_B + r0 + kcb + 16);
                al[3] = *(const uint32_t*)(pA + TILE_B + r1 + kcb + 16);
                #pragma unroll
                for (int nt = 0; nt < 8; nt++) {
                    mma_bf16(acc[mt][nt], al, bh[nt]);   // small terms first
                    mma_bf16(acc[mt][nt], ah, bl[nt]);
                    mma_bf16(acc[mt][nt], ah, bh[nt]);
                }
            }
        }
        __syncthreads();
    }

    // ---- epilogue ----
    if (Cf) {
        Cf += (size_t)blockIdx.z * sC;
        #pragma unroll
        for (int mt = 0; mt < 4; mt++) {
            const int row = m0 + warp_m * 64 + mt * 16 + g;
            #pragma unroll
            for (int nt = 0; nt < 8; nt++) {
                const int col = n0 + warp_n * 64 + nt * 8 + 2 * c;
                *(float2*)(Cf + (size_t)row * N + col) =
                    make_float2(acc[mt][nt][0] * alpha, acc[mt][nt][1] * alpha);
                *(float2*)(Cf + (size_t)(row + 8) * N + col) =
                    make_float2(acc[mt][nt][2] * alpha, acc[mt][nt][3] * alpha);
            }
        }
    } else {
        Ch += (size_t)blockIdx.z * sC;
        Cl += (size_t)blockIdx.z * sC;
        #pragma unroll
        for (int mt = 0; mt < 4; mt++) {
            const int row = m0 + warp_m * 64 + mt * 16 + g;
            #pragma unroll
            for (int nt = 0; nt < 8; nt++) {
                const int col = n0 + warp_n * 64 + nt * 8 + 2 * c;
                uint32_t h, l;
                pack_split(acc[mt][nt][0] * alpha, acc[mt][nt][1] * alpha, h, l);
                *(uint32_t*)(Ch + (size_t)row * N + col) = h;
                *(uint32_t*)(Cl + (size_t)row * N + col) = l;
                pack_split(acc[mt][nt][2] * alpha, acc[mt][nt][3] * alpha, h, l);
                *(uint32_t*)(Ch + (size_t)(row + 8) * N + col) = h;
                *(uint32_t*)(Cl + (size_t)(row + 8) * N + col) = l;
            }
        }
    }
}

// ============================================================================
// Masked softmax over rows of attn [BATCH*NQ, NKV] -> split bf16 probs.
// ============================================================================
__global__ void __launch_bounds__(256) softmax_split_kernel(
    const float* __restrict__ attn, const int* __restrict__ mask,
    __nv_bfloat16* __restrict__ Ph, __nv_bfloat16* __restrict__ Pl)
{
    const int row = blockIdx.x;
    const int b   = row >> 10;             // NQ = 1024
    const float2* p = (const float2*)(attn + (size_t)row * NKV);
    const int2* mrow = (const int2*)(mask + b * NKV);

    float2 v[8];
    float mx = -3.0e38f;
    #pragma unroll
    for (int i = 0; i < 8; i++) {
        int m2 = threadIdx.x + i * 256;
        float2 x = p[m2];
        int2 mm = mrow[m2];
        x.x += mm.x ? 0.0f : -10000.0f;
        x.y += mm.y ? 0.0f : -10000.0f;
        v[i] = x;
        mx = fmaxf(mx, fmaxf(x.x, x.y));
    }

    __shared__ float red[8];
    #pragma unroll
    for (int o = 16; o; o >>= 1) mx = fmaxf(mx, __shfl_xor_sync(0xffffffffu, mx, o));
    if ((threadIdx.x & 31) == 0) red[threadIdx.x >> 5] = mx;
    __syncthreads();
    float bm = red[0];
    #pragma unroll
    for (int w = 1; w < 8; w++) bm = fmaxf(bm, red[w]);
    __syncthreads();

    float sum = 0.0f;
    #pragma unroll
    for (int i = 0; i < 8; i++) {
        v[i].x = __expf(v[i].x - bm);
        v[i].y = __expf(v[i].y - bm);
        sum += v[i].x + v[i].y;
    }
    #pragma unroll
    for (int o = 16; o; o >>= 1) sum += __shfl_xor_sync(0xffffffffu, sum, o);
    if ((threadIdx.x & 31) == 0) red[threadIdx.x >> 5] = sum;
    __syncthreads();
    float ts = red[0];
    #pragma unroll
    for (int w = 1; w < 8; w++) ts += red[w];
    float inv = 1.0f / ts;

    #pragma unroll
    for (int i = 0; i < 8; i++) {
        int m2 = threadIdx.x + i * 256;
        uint32_t h, l;
        pack_split(v[i].x * inv, v[i].y * inv, h, l);
        *(uint32_t*)(Ph + (size_t)row * NKV + 2 * m2) = h;
        *(uint32_t*)(Pl + (size_t)row * NKV + 2 * m2) = l;
    }
}

// ============================================================================
// launch
// ============================================================================
extern "C" void kernel_launch(void* const* d_in, const int* in_sizes, int n_in,
                              void* d_out, int out_size)
{
    const float* prototype = (const float*)d_in[0];   // [B, NQ, DIM]
    const float* q_x       = (const float*)d_in[1];   // [B, NKV, DIM]
    const int*   mask      = (const int*)  d_in[2];   // [B, NKV]
    const float* Wq        = (const float*)d_in[3];
    const float* Wk        = (const float*)d_in[4];
    const float* Wv        = (const float*)d_in[5];
    const float* Wproj     = (const float*)d_in[6];
    float* out = (float*)d_out;                        // [B, NQ, DIM] fp32

    __nv_bfloat16 *ph, *pl, *xh, *xl, *wqh, *wql, *wkh, *wkl, *wvh, *wvl,
                  *wph, *wpl, *qh, *ql, *kh, *kl, *vth, *vtl, *aph, *apl, *oh, *ol;
    float* attn;
    cudaGetSymbolAddress((void**)&ph,  s_ph);  cudaGetSymbolAddress((void**)&pl,  s_pl);
    cudaGetSymbolAddress((void**)&xh,  s_xh);  cudaGetSymbolAddress((void**)&xl,  s_xl);
    cudaGetSymbolAddress((void**)&wqh, s_wqh); cudaGetSymbolAddress((void**)&wql, s_wql);
    cudaGetSymbolAddress((void**)&wkh, s_wkh); cudaGetSymbolAddress((void**)&wkl, s_wkl);
    cudaGetSymbolAddress((void**)&wvh, s_wvh); cudaGetSymbolAddress((void**)&wvl, s_wvl);
    cudaGetSymbolAddress((void**)&wph, s_wph); cudaGetSymbolAddress((void**)&wpl, s_wpl);
    cudaGetSymbolAddress((void**)&qh,  s_qh);  cudaGetSymbolAddress((void**)&ql,  s_ql);
    cudaGetSymbolAddress((void**)&kh,  s_kh);  cudaGetSymbolAddress((void**)&kl,  s_kl);
    cudaGetSymbolAddress((void**)&vth, s_vth); cudaGetSymbolAddress((void**)&vtl, s_vtl);
    cudaGetSymbolAddress((void**)&aph, s_aph); cudaGetSymbolAddress((void**)&apl, s_apl);
    cudaGetSymbolAddress((void**)&oh,  s_oh);  cudaGetSymbolAddress((void**)&ol,  s_ol);
    cudaGetSymbolAddress((void**)&attn, g_attn);

    cudaFuncSetAttribute(gemm_nt_split,
                         cudaFuncAttributeMaxDynamicSharedMemorySize, GEMM_SMEM);

    const float scale = 0.04419417382415922f;  // 1/sqrt(512)
    dim3 blk(128);

    // ---- split external inputs ----
    split_kernel<<<(BATCH*NQ*DIM/4 + 255)/256, 256>>>(prototype, ph, pl, BATCH*NQ*DIM/4);
    split_kernel<<<(BATCH*NKV*DIM/4 + 255)/256, 256>>>(q_x, xh, xl, BATCH*NKV*DIM/4);
    split_kernel<<<(DIM*DIM/4 + 255)/256, 256>>>(Wq, wqh, wql, DIM*DIM/4);
    split_kernel<<<(DIM*DIM/4 + 255)/256, 256>>>(Wk, wkh, wkl, DIM*DIM/4);
    split_kernel<<<(DIM*DIM/4 + 255)/256, 256>>>(Wv, wvh, wvl, DIM*DIM/4);
    split_kernel<<<(DIM*DIM/4 + 255)/256, 256>>>(Wproj, wph, wpl, DIM*DIM/4);

    // q = prototype @ Wq^T : M=8192, N=512, K=512 -> split
    gemm_nt_split<<<dim3(DIM/128, (BATCH*NQ)/128, 1), blk, GEMM_SMEM>>>(
        ph, pl, wqh, wql, nullptr, qh, ql,
        BATCH*NQ, DIM, DIM, 0, 0, 0, 1.0f);

    // k = q_x @ Wk^T : M=32768, N=512, K=512 -> split
    gemm_nt_split<<<dim3(DIM/128, (BATCH*NKV)/128, 1), blk, GEMM_SMEM>>>(
        xh, xl, wkh, wkl, nullptr, kh, kl,
        BATCH*NKV, DIM, DIM, 0, 0, 0, 1.0f);

    // vT[b] = Wv @ q_x[b]^T : per batch M=512, N=4096, K=512 -> split
    gemm_nt_split<<<dim3(NKV/128, DIM/128, BATCH), blk, GEMM_SMEM>>>(
        wvh, wvl, xh, xl, nullptr, vth, vtl,
        DIM, NKV, DIM, 0, (size_t)NKV*DIM, (size_t)DIM*NKV, 1.0f);

    // attn[b] = scale * q[b] @ k[b]^T : M=1024, N=4096, K=512 -> fp32
    gemm_nt_split<<<dim3(NKV/128, NQ/128, BATCH), blk, GEMM_SMEM>>>(
        qh, ql, kh, kl, attn, nullptr, nullptr,
        NQ, NKV, DIM, (size_t)NQ*DIM, (size_t)NKV*DIM, (size_t)NQ*NKV, scale);

    // masked softmax -> split probs
    softmax_split_kernel<<<BATCH*NQ, 256>>>(attn, mask, aph, apl);

    // x[b] = P[b] @ vT[b]^T : M=1024, N=512, K=4096 -> split
    gemm_nt_split<<<dim3(DIM/128, NQ/128, BATCH), blk, GEMM_SMEM>>>(
        aph, apl, vth, vtl, nullptr, oh, ol,
        NQ, DIM, NKV, (size_t)NQ*NKV, (size_t)DIM*NKV, (size_t)NQ*DIM, 1.0f);

    // out = x @ Wproj^T : M=8192, N=512, K=512 -> fp32
    gemm_nt_split<<<dim3(DIM/128, (BATCH*NQ)/128, 1), blk, GEMM_SMEM>>>(
        oh, ol, wph, wpl, out, nullptr, nullptr,
        BATCH*NQ, DIM, DIM, 0, 0, 0, 1.0f);
}

// round 8
// speedup vs baseline: 1.1617x; 1.1017x over previous
#include <cuda_runtime.h>
#include <cuda_bf16.h>
#include <cstdint>
#include <math.h>

#define BATCH 8
#define NQ    1024
#define NKV   4096
#define DIM   512

// ---------------- scratch (device globals: allocation-free) ----------------
__device__ __align__(16) __nv_bfloat16 s_ph [BATCH*NQ*DIM],  s_pl [BATCH*NQ*DIM];   // prototype
__device__ __align__(16) __nv_bfloat16 s_xh [BATCH*NKV*DIM], s_xl [BATCH*NKV*DIM];  // q_x
__device__ __align__(16) __nv_bfloat16 s_wqh[DIM*DIM], s_wql[DIM*DIM];
__device__ __align__(16) __nv_bfloat16 s_wkh[DIM*DIM], s_wkl[DIM*DIM];
__device__ __align__(16) __nv_bfloat16 s_wvh[DIM*DIM], s_wvl[DIM*DIM];
__device__ __align__(16) __nv_bfloat16 s_wph[DIM*DIM], s_wpl[DIM*DIM];
__device__ __align__(16) __nv_bfloat16 s_qh [BATCH*NQ*DIM],  s_ql [BATCH*NQ*DIM];   // q
__device__ __align__(16) __nv_bfloat16 s_kh [BATCH*NKV*DIM], s_kl [BATCH*NKV*DIM];  // k
__device__ __align__(16) __nv_bfloat16 s_vth[BATCH*DIM*NKV], s_vtl[BATCH*DIM*NKV];  // vT
__device__ __align__(16) __nv_bfloat16 s_aph[(size_t)BATCH*NQ*NKV];                 // probs hi
__device__ __align__(16) __nv_bfloat16 s_apl[(size_t)BATCH*NQ*NKV];                 // probs lo
__device__ __align__(16) __nv_bfloat16 s_oh [BATCH*NQ*DIM],  s_ol [BATCH*NQ*DIM];   // x
__device__ __align__(16) float g_attn[(size_t)BATCH*NQ*NKV];                        // fp32 scores

// ============================================================================
// helpers
// ============================================================================
__device__ __forceinline__ uint32_t smem_u32(const void* p) {
    uint32_t a;
    asm("{ .reg .u64 t; cvta.to.shared.u64 t, %1; cvt.u32.u64 %0, t; }"
        : "=r"(a) : "l"(p));
    return a;
}
__device__ __forceinline__ void cp_async16(uint32_t saddr, const void* gaddr) {
    asm volatile("cp.async.ca.shared.global [%0], [%1], 16;"
                 :: "r"(saddr), "l"(gaddr) : "memory");
}
__device__ __forceinline__ void cp_commit() {
    asm volatile("cp.async.commit_group;" ::: "memory");
}
__device__ __forceinline__ void cp_wait1() {
    asm volatile("cp.async.wait_group 1;" ::: "memory");
}
__device__ __forceinline__ void cp_wait0() {
    asm volatile("cp.async.wait_group 0;" ::: "memory");
}

// mma.sync m16n8k16 bf16: d += a*b (f32 accumulators in-place)
__device__ __forceinline__ void mma_bf16(float* d, const uint32_t* a, const uint32_t* b) {
    asm volatile(
        "mma.sync.aligned.m16n8k16.row.col.f32.bf16.bf16.f32 "
        "{%0,%1,%2,%3}, {%4,%5,%6,%7}, {%8,%9}, {%0,%1,%2,%3};"
        : "+f"(d[0]), "+f"(d[1]), "+f"(d[2]), "+f"(d[3])
        : "r"(a[0]), "r"(a[1]), "r"(a[2]), "r"(a[3]), "r"(b[0]), "r"(b[1]));
}

// ldmatrix.x4: four 8x8 b16 matrices; per-lane address in addr
__device__ __forceinline__ void ldsm_x4(uint32_t& r0, uint32_t& r1,
                                        uint32_t& r2, uint32_t& r3, uint32_t addr) {
    asm volatile("ldmatrix.sync.aligned.m8n8.x4.shared.b16 {%0,%1,%2,%3}, [%4];"
                 : "=r"(r0), "=r"(r1), "=r"(r2), "=r"(r3) : "r"(addr));
}

// split (x,y) -> packed bf16x2 hi (x in low 16) + packed bf16x2 lo residuals
__device__ __forceinline__ void pack_split(float x, float y, uint32_t& h, uint32_t& l) {
    asm("cvt.rn.bf16x2.f32 %0, %1, %2;" : "=r"(h) : "f"(y), "f"(x));
    float h0 = __uint_as_float(h << 16);
    float h1 = __uint_as_float(h & 0xFFFF0000u);
    asm("cvt.rn.bf16x2.f32 %0, %1, %2;" : "=r"(l) : "f"(y - h1), "f"(x - h0));
}

// ============================================================================
// elementwise fp32 -> (hi, lo) bf16 split, 4 floats per thread
// ============================================================================
__global__ void __launch_bounds__(256) split_kernel(
    const float* __restrict__ in, __nv_bfloat16* __restrict__ h,
    __nv_bfloat16* __restrict__ l, int n4)
{
    int i = blockIdx.x * 256 + threadIdx.x;
    if (i >= n4) return;
    float4 v = ((const float4*)in)[i];
    uint32_t h0, l0, h1, l1;
    pack_split(v.x, v.y, h0, l0);
    pack_split(v.z, v.w, h1, l1);
    ((uint2*)h)[i] = make_uint2(h0, h1);
    ((uint2*)l)[i] = make_uint2(l0, l1);
}

// split all 4 weight matrices in one launch (blockIdx.y selects matrix)
__global__ void __launch_bounds__(256) split4_kernel(
    const float* __restrict__ w0, const float* __restrict__ w1,
    const float* __restrict__ w2, const float* __restrict__ w3,
    __nv_bfloat16* __restrict__ h0o, __nv_bfloat16* __restrict__ l0o,
    __nv_bfloat16* __restrict__ h1o, __nv_bfloat16* __restrict__ l1o,
    __nv_bfloat16* __restrict__ h2o, __nv_bfloat16* __restrict__ l2o,
    __nv_bfloat16* __restrict__ h3o, __nv_bfloat16* __restrict__ l3o,
    int n4)
{
    int i = blockIdx.x * 256 + threadIdx.x;
    if (i >= n4) return;
    const float* in = blockIdx.y == 0 ? w0 : blockIdx.y == 1 ? w1
                    : blockIdx.y == 2 ? w2 : w3;
    __nv_bfloat16* h = blockIdx.y == 0 ? h0o : blockIdx.y == 1 ? h1o
                     : blockIdx.y == 2 ? h2o : h3o;
    __nv_bfloat16* l = blockIdx.y == 0 ? l0o : blockIdx.y == 1 ? l1o
                     : blockIdx.y == 2 ? l2o : l3o;
    float4 v = ((const float4*)in)[i];
    uint32_t ha, la, hb, lb;
    pack_split(v.x, v.y, ha, la);
    pack_split(v.z, v.w, hb, lb);
    ((uint2*)h)[i] = make_uint2(ha, hb);
    ((uint2*)l)[i] = make_uint2(la, lb);
}

// ============================================================================
// bf16x3 GEMM NT on pre-split operands, warp tile 64x64, ldmatrix fragments:
//   C[M,N] = alpha * (Ah+Al)[M,K] @ (Bh+Bl)[N,K]^T   (lo*lo dropped)
// CTA tile 128x128, 128 threads (4 warps, 2x2), K-tile 32 (2 x k16),
// 2-stage cp.async. SMEM rows = 40 bf16 (80B): each 8-row LDSM phase hits
// all 32 banks (conflict-free); 32 LDSM.x4 replace 128 LDS.32 per k-tile.
// Output: fp32 (Cf) OR split bf16 (Ch, Cl).
// blockIdx.z = batch; sA/sB/sC per-batch element strides (0 = broadcast).
// M,N % 128 == 0, K % 32 == 0.
// ============================================================================
#define PAD2      40                       // bf16 per smem row
#define ROW_B     (PAD2 * 2)               // 80 bytes per row
#define TILE_B    (128 * ROW_B)            // bytes per tile (10240)
#define STAGE_B   (4 * TILE_B)             // Ah, Al, Bh, Bl (40960)
#define GEMM_SMEM (2 * STAGE_B)            // 81920

__global__ void __launch_bounds__(128, 2) gemm_nt_split(
    const __nv_bfloat16* __restrict__ Ah, const __nv_bfloat16* __restrict__ Al,
    const __nv_bfloat16* __restrict__ Bh, const __nv_bfloat16* __restrict__ Bl,
    float* __restrict__ Cf,
    __nv_bfloat16* __restrict__ Ch, __nv_bfloat16* __restrict__ Cl,
    int M, int N, int K, size_t sA, size_t sB, size_t sC, float alpha)
{
    extern __shared__ __align__(16) char smem[];
    const uint32_t sbase = smem_u32(smem);

    const int t    = threadIdx.x;
    const int wid  = t >> 5;
    const int lane = t & 31;
    const int g    = lane >> 2;
    const int c    = lane & 3;
    const int warp_m = wid >> 1;    // 0..1
    const int warp_n = wid & 1;     // 0..1

    // ldmatrix per-lane addressing components
    const uint32_t a_row = lane & 15;            // row within the 16-row mt block
    const uint32_t a_kh  = (lane >> 4) * 16;     // k-half byte offset
    const uint32_t b_row = (lane & 7) + ((lane >> 4) << 3);  // row within nt-pair (16 rows)
    const uint32_t b_kh  = ((lane >> 3) & 1) * 16;

    Ah += (size_t)blockIdx.z * sA;  Al += (size_t)blockIdx.z * sA;
    Bh += (size_t)blockIdx.z * sB;  Bl += (size_t)blockIdx.z * sB;
    const int m0 = blockIdx.y * 128;
    const int n0 = blockIdx.x * 128;

    // ---- async load of one K-tile (32 bf16 wide) for all 4 arrays ----
    auto load_tile = [&](int kt, int s) {
        const uint32_t st = sbase + (uint32_t)(s * STAGE_B);
        const int kb = kt * 32;
        #pragma unroll
        for (int ph = 0; ph < 4; ph++) {
            int idx = ph * 128 + t;          // 0..511
            int row = idx >> 2;              // 0..127
            int c4  = idx & 3;               // 16B chunk (8 bf16)
            uint32_t so = (uint32_t)(row * ROW_B + c4 * 16);
            const size_t ga = (size_t)(m0 + row) * K + kb + c4 * 8;
            const size_t gb = (size_t)(n0 + row) * K + kb + c4 * 8;
            cp_async16(st + 0 * TILE_B + so, Ah + ga);
            cp_async16(st + 1 * TILE_B + so, Al + ga);
            cp_async16(st + 2 * TILE_B + so, Bh + gb);
            cp_async16(st + 3 * TILE_B + so, Bl + gb);
        }
        cp_commit();
    };

    float acc[4][8][4] = {};   // [mtile 16-rows][ntile 8-cols][reg]

    const int nkt = K >> 5;
    load_tile(0, 0);

    for (int kt = 0; kt < nkt; kt++) {
        const int s = kt & 1;
        if (kt + 1 < nkt) {
            load_tile(kt + 1, s ^ 1);
            cp_wait1();
        } else {
            cp_wait0();
        }
        __syncthreads();

        const uint32_t aB = sbase + s * STAGE_B + warp_m * 64 * ROW_B;
        const uint32_t bB = sbase + s * STAGE_B + 2 * TILE_B + warp_n * 64 * ROW_B;

        #pragma unroll
        for (int ks2 = 0; ks2 < 2; ks2++) {
            const uint32_t kso = ks2 * 32;

            // B fragments for all 8 n-tiles via 4+4 LDSM.x4 (2 nt per LDSM)
            uint32_t bh[8][2], bl[8][2];
            #pragma unroll
            for (int p = 0; p < 4; p++) {
                uint32_t addr = bB + (p * 16 + b_row) * ROW_B + kso + b_kh;
                ldsm_x4(bh[2*p][0], bh[2*p][1], bh[2*p+1][0], bh[2*p+1][1], addr);
                ldsm_x4(bl[2*p][0], bl[2*p][1], bl[2*p+1][0], bl[2*p+1][1],
                        addr + TILE_B);
            }

            #pragma unroll
            for (int mt = 0; mt < 4; mt++) {
                uint32_t addr = aB + (mt * 16 + a_row) * ROW_B + kso + a_kh;
                uint32_t ah[4], al[4];
                ldsm_x4(ah[0], ah[1], ah[2], ah[3], addr);
                ldsm_x4(al[0], al[1], al[2], al[3], addr + TILE_B);
                #pragma unroll
                for (int nt = 0; nt < 8; nt++) {
                    mma_bf16(acc[mt][nt], al, bh[nt]);   // small terms first
                    mma_bf16(acc[mt][nt], ah, bl[nt]);
                    mma_bf16(acc[mt][nt], ah, bh[nt]);
                }
            }
        }
        __syncthreads();
    }

    // ---- epilogue ----
    if (Cf) {
        Cf += (size_t)blockIdx.z * sC;
        #pragma unroll
        for (int mt = 0; mt < 4; mt++) {
            const int row = m0 + warp_m * 64 + mt * 16 + g;
            #pragma unroll
            for (int nt = 0; nt < 8; nt++) {
                const int col = n0 + warp_n * 64 + nt * 8 + 2 * c;
                *(float2*)(Cf + (size_t)row * N + col) =
                    make_float2(acc[mt][nt][0] * alpha, acc[mt][nt][1] * alpha);
                *(float2*)(Cf + (size_t)(row + 8) * N + col) =
                    make_float2(acc[mt][nt][2] * alpha, acc[mt][nt][3] * alpha);
            }
        }
    } else {
        Ch += (size_t)blockIdx.z * sC;
        Cl += (size_t)blockIdx.z * sC;
        #pragma unroll
        for (int mt = 0; mt < 4; mt++) {
            const int row = m0 + warp_m * 64 + mt * 16 + g;
            #pragma unroll
            for (int nt = 0; nt < 8; nt++) {
                const int col = n0 + warp_n * 64 + nt * 8 + 2 * c;
                uint32_t h, l;
                pack_split(acc[mt][nt][0] * alpha, acc[mt][nt][1] * alpha, h, l);
                *(uint32_t*)(Ch + (size_t)row * N + col) = h;
                *(uint32_t*)(Cl + (size_t)row * N + col) = l;
                pack_split(acc[mt][nt][2] * alpha, acc[mt][nt][3] * alpha, h, l);
                *(uint32_t*)(Ch + (size_t)(row + 8) * N + col) = h;
                *(uint32_t*)(Cl + (size_t)(row + 8) * N + col) = l;
            }
        }
    }
}

// ============================================================================
// Masked softmax over rows of attn [BATCH*NQ, NKV] -> split bf16 probs.
// ============================================================================
__global__ void __launch_bounds__(256) softmax_split_kernel(
    const float* __restrict__ attn, const int* __restrict__ mask,
    __nv_bfloat16* __restrict__ Ph, __nv_bfloat16* __restrict__ Pl)
{
    const int row = blockIdx.x;
    const int b   = row >> 10;             // NQ = 1024
    const float2* p = (const float2*)(attn + (size_t)row * NKV);
    const int2* mrow = (const int2*)(mask + b * NKV);

    float2 v[8];
    float mx = -3.0e38f;
    #pragma unroll
    for (int i = 0; i < 8; i++) {
        int m2 = threadIdx.x + i * 256;
        float2 x = p[m2];
        int2 mm = mrow[m2];
        x.x += mm.x ? 0.0f : -10000.0f;
        x.y += mm.y ? 0.0f : -10000.0f;
        v[i] = x;
        mx = fmaxf(mx, fmaxf(x.x, x.y));
    }

    __shared__ float red[8];
    #pragma unroll
    for (int o = 16; o; o >>= 1) mx = fmaxf(mx, __shfl_xor_sync(0xffffffffu, mx, o));
    if ((threadIdx.x & 31) == 0) red[threadIdx.x >> 5] = mx;
    __syncthreads();
    float bm = red[0];
    #pragma unroll
    for (int w = 1; w < 8; w++) bm = fmaxf(bm, red[w]);
    __syncthreads();

    float sum = 0.0f;
    #pragma unroll
    for (int i = 0; i < 8; i++) {
        v[i].x = __expf(v[i].x - bm);
        v[i].y = __expf(v[i].y - bm);
        sum += v[i].x + v[i].y;
    }
    #pragma unroll
    for (int o = 16; o; o >>= 1) sum += __shfl_xor_sync(0xffffffffu, sum, o);
    if ((threadIdx.x & 31) == 0) red[threadIdx.x >> 5] = sum;
    __syncthreads();
    float ts = red[0];
    #pragma unroll
    for (int w = 1; w < 8; w++) ts += red[w];
    float inv = 1.0f / ts;

    #pragma unroll
    for (int i = 0; i < 8; i++) {
        int m2 = threadIdx.x + i * 256;
        uint32_t h, l;
        pack_split(v[i].x * inv, v[i].y * inv, h, l);
        *(uint32_t*)(Ph + (size_t)row * NKV + 2 * m2) = h;
        *(uint32_t*)(Pl + (size_t)row * NKV + 2 * m2) = l;
    }
}

// ============================================================================
// launch
// ============================================================================
extern "C" void kernel_launch(void* const* d_in, const int* in_sizes, int n_in,
                              void* d_out, int out_size)
{
    const float* prototype = (const float*)d_in[0];   // [B, NQ, DIM]
    const float* q_x       = (const float*)d_in[1];   // [B, NKV, DIM]
    const int*   mask      = (const int*)  d_in[2];   // [B, NKV]
    const float* Wq        = (const float*)d_in[3];
    const float* Wk        = (const float*)d_in[4];
    const float* Wv        = (const float*)d_in[5];
    const float* Wproj     = (const float*)d_in[6];
    float* out = (float*)d_out;                        // [B, NQ, DIM] fp32

    __nv_bfloat16 *ph, *pl, *xh, *xl, *wqh, *wql, *wkh, *wkl, *wvh, *wvl,
                  *wph, *wpl, *qh, *ql, *kh, *kl, *vth, *vtl, *aph, *apl, *oh, *ol;
    float* attn;
    cudaGetSymbolAddress((void**)&ph,  s_ph);  cudaGetSymbolAddress((void**)&pl,  s_pl);
    cudaGetSymbolAddress((void**)&xh,  s_xh);  cudaGetSymbolAddress((void**)&xl,  s_xl);
    cudaGetSymbolAddress((void**)&wqh, s_wqh); cudaGetSymbolAddress((void**)&wql, s_wql);
    cudaGetSymbolAddress((void**)&wkh, s_wkh); cudaGetSymbolAddress((void**)&wkl, s_wkl);
    cudaGetSymbolAddress((void**)&wvh, s_wvh); cudaGetSymbolAddress((void**)&wvl, s_wvl);
    cudaGetSymbolAddress((void**)&wph, s_wph); cudaGetSymbolAddress((void**)&wpl, s_wpl);
    cudaGetSymbolAddress((void**)&qh,  s_qh);  cudaGetSymbolAddress((void**)&ql,  s_ql);
    cudaGetSymbolAddress((void**)&kh,  s_kh);  cudaGetSymbolAddress((void**)&kl,  s_kl);
    cudaGetSymbolAddress((void**)&vth, s_vth); cudaGetSymbolAddress((void**)&vtl, s_vtl);
    cudaGetSymbolAddress((void**)&aph, s_aph); cudaGetSymbolAddress((void**)&apl, s_apl);
    cudaGetSymbolAddress((void**)&oh,  s_oh);  cudaGetSymbolAddress((void**)&ol,  s_ol);
    cudaGetSymbolAddress((void**)&attn, g_attn);

    cudaFuncSetAttribute(gemm_nt_split,
                         cudaFuncAttributeMaxDynamicSharedMemorySize, GEMM_SMEM);

    const float scale = 0.04419417382415922f;  // 1/sqrt(512)
    dim3 blk(128);

    // ---- split external inputs ----
    split_kernel<<<(BATCH*NQ*DIM/4 + 255)/256, 256>>>(prototype, ph, pl, BATCH*NQ*DIM/4);
    split_kernel<<<(BATCH*NKV*DIM/4 + 255)/256, 256>>>(q_x, xh, xl, BATCH*NKV*DIM/4);
    split4_kernel<<<dim3((DIM*DIM/4 + 255)/256, 4), 256>>>(
        Wq, Wk, Wv, Wproj, wqh, wql, wkh, wkl, wvh, wvl, wph, wpl, DIM*DIM/4);

    // q = prototype @ Wq^T : M=8192, N=512, K=512 -> split
    gemm_nt_split<<<dim3(DIM/128, (BATCH*NQ)/128, 1), blk, GEMM_SMEM>>>(
        ph, pl, wqh, wql, nullptr, qh, ql,
        BATCH*NQ, DIM, DIM, 0, 0, 0, 1.0f);

    // k = q_x @ Wk^T : M=32768, N=512, K=512 -> split
    gemm_nt_split<<<dim3(DIM/128, (BATCH*NKV)/128, 1), blk, GEMM_SMEM>>>(
        xh, xl, wkh, wkl, nullptr, kh, kl,
        BATCH*NKV, DIM, DIM, 0, 0, 0, 1.0f);

    // vT[b] = Wv @ q_x[b]^T : per batch M=512, N=4096, K=512 -> split
    gemm_nt_split<<<dim3(NKV/128, DIM/128, BATCH), blk, GEMM_SMEM>>>(
        wvh, wvl, xh, xl, nullptr, vth, vtl,
        DIM, NKV, DIM, 0, (size_t)NKV*DIM, (size_t)DIM*NKV, 1.0f);

    // attn[b] = scale * q[b] @ k[b]^T : M=1024, N=4096, K=512 -> fp32
    gemm_nt_split<<<dim3(NKV/128, NQ/128, BATCH), blk, GEMM_SMEM>>>(
        qh, ql, kh, kl, attn, nullptr, nullptr,
        NQ, NKV, DIM, (size_t)NQ*DIM, (size_t)NKV*DIM, (size_t)NQ*NKV, scale);

    // masked softmax -> split probs
    softmax_split_kernel<<<BATCH*NQ, 256>>>(attn, mask, aph, apl);

    // x[b] = P[b] @ vT[b]^T : M=1024, N=512, K=4096 -> split
    gemm_nt_split<<<dim3(DIM/128, NQ/128, BATCH), blk, GEMM_SMEM>>>(
        aph, apl, vth, vtl, nullptr, oh, ol,
        NQ, DIM, NKV, (size_t)NQ*NKV, (size_t)DIM*NKV, (size_t)NQ*DIM, 1.0f);

    // out = x @ Wproj^T : M=8192, N=512, K=512 -> fp32
    gemm_nt_split<<<dim3(DIM/128, (BATCH*NQ)/128, 1), blk, GEMM_SMEM>>>(
        oh, ol, wph, wpl, out, nullptr, nullptr,
        BATCH*NQ, DIM, DIM, 0, 0, 0, 1.0f);
}

// round 9
// speedup vs baseline: 1.9019x; 1.6372x over previous
#include <cuda_runtime.h>
#include <cuda_bf16.h>
#include <cstdint>
#include <math.h>

#define BATCH 8
#define NQ    1024
#define NKV   4096
#define DIM   512

// ---------------- scratch (device globals: allocation-free) ----------------
__device__ __align__(16) __nv_bfloat16 s_ph [BATCH*NQ*DIM],  s_pl [BATCH*NQ*DIM];   // prototype split
__device__ __align__(16) __nv_bfloat16 s_xh [BATCH*NKV*DIM], s_xl [BATCH*NKV*DIM];  // compacted q_x split
__device__ __align__(16) __nv_bfloat16 s_wqh[DIM*DIM], s_wql[DIM*DIM];
__device__ __align__(16) __nv_bfloat16 s_wkh[DIM*DIM], s_wkl[DIM*DIM];
__device__ __align__(16) __nv_bfloat16 s_wvh[DIM*DIM], s_wvl[DIM*DIM];
__device__ __align__(16) __nv_bfloat16 s_wph[DIM*DIM], s_wpl[DIM*DIM];
__device__ __align__(16) __nv_bfloat16 s_qh [BATCH*NQ*DIM],  s_ql [BATCH*NQ*DIM];   // q split
__device__ __align__(16) __nv_bfloat16 s_kh [BATCH*NKV*DIM], s_kl [BATCH*NKV*DIM];  // compacted k split
__device__ __align__(16) __nv_bfloat16 s_vth[BATCH*DIM*NKV], s_vtl[BATCH*DIM*NKV];  // compacted vT split
__device__ __align__(16) __nv_bfloat16 s_aph[(size_t)BATCH*NQ*NKV];                 // compacted probs hi
__device__ __align__(16) __nv_bfloat16 s_apl[(size_t)BATCH*NQ*NKV];                 // compacted probs lo
__device__ __align__(16) __nv_bfloat16 s_oh [BATCH*NQ*DIM],  s_ol [BATCH*NQ*DIM];   // x split
__device__ __align__(16) float g_attn[(size_t)BATCH*NQ*NKV];                        // compacted scores
__device__ int g_idx[BATCH*NKV];   // kept-position indices per batch
__device__ int g_cnt[BATCH];       // kept count
__device__ int g_cntp[BATCH];      // kept count padded to x128

// ============================================================================
// helpers
// ============================================================================
__device__ __forceinline__ uint32_t smem_u32(const void* p) {
    uint32_t a;
    asm("{ .reg .u64 t; cvta.to.shared.u64 t, %1; cvt.u32.u64 %0, t; }"
        : "=r"(a) : "l"(p));
    return a;
}
__device__ __forceinline__ void cp_async16(uint32_t saddr, const void* gaddr) {
    asm volatile("cp.async.ca.shared.global [%0], [%1], 16;"
                 :: "r"(saddr), "l"(gaddr) : "memory");
}
__device__ __forceinline__ void cp_commit() {
    asm volatile("cp.async.commit_group;" ::: "memory");
}
__device__ __forceinline__ void cp_wait1() {
    asm volatile("cp.async.wait_group 1;" ::: "memory");
}
__device__ __forceinline__ void cp_wait0() {
    asm volatile("cp.async.wait_group 0;" ::: "memory");
}

// mma.sync m16n8k16 bf16: d += a*b (f32 accumulators in-place)
__device__ __forceinline__ void mma_bf16(float* d, const uint32_t* a, const uint32_t* b) {
    asm volatile(
        "mma.sync.aligned.m16n8k16.row.col.f32.bf16.bf16.f32 "
        "{%0,%1,%2,%3}, {%4,%5,%6,%7}, {%8,%9}, {%0,%1,%2,%3};"
        : "+f"(d[0]), "+f"(d[1]), "+f"(d[2]), "+f"(d[3])
        : "r"(a[0]), "r"(a[1]), "r"(a[2]), "r"(a[3]), "r"(b[0]), "r"(b[1]));
}

__device__ __forceinline__ void ldsm_x4(uint32_t& r0, uint32_t& r1,
                                        uint32_t& r2, uint32_t& r3, uint32_t addr) {
    asm volatile("ldmatrix.sync.aligned.m8n8.x4.shared.b16 {%0,%1,%2,%3}, [%4];"
                 : "=r"(r0), "=r"(r1), "=r"(r2), "=r"(r3) : "r"(addr));
}

// split (x,y) -> packed bf16x2 hi (x in low 16) + packed bf16x2 lo residuals
__device__ __forceinline__ void pack_split(float x, float y, uint32_t& h, uint32_t& l) {
    asm("cvt.rn.bf16x2.f32 %0, %1, %2;" : "=r"(h) : "f"(y), "f"(x));
    float h0 = __uint_as_float(h << 16);
    float h1 = __uint_as_float(h & 0xFFFF0000u);
    asm("cvt.rn.bf16x2.f32 %0, %1, %2;" : "=r"(l) : "f"(y - h1), "f"(x - h0));
}

// ============================================================================
// mask scan: per batch, build compact index list of kept positions
// ============================================================================
__global__ void __launch_bounds__(1024) mask_scan_kernel(
    const int* __restrict__ mask, int* __restrict__ idx,
    int* __restrict__ cnt, int* __restrict__ cntp)
{
    const int b = blockIdx.x;
    const int t = threadIdx.x;
    const int* m = mask + b * NKV;
    __shared__ int sums[1024];

    int v[4], s = 0;
    #pragma unroll
    for (int i = 0; i < 4; i++) { v[i] = m[t * 4 + i] ? 1 : 0; s += v[i]; }
    sums[t] = s;
    __syncthreads();

    // Hillis-Steele inclusive scan
    for (int off = 1; off < 1024; off <<= 1) {
        int x = (t >= off) ? sums[t - off] : 0;
        __syncthreads();
        sums[t] += x;
        __syncthreads();
    }

    int o = sums[t] - s;   // exclusive base for this thread
    #pragma unroll
    for (int i = 0; i < 4; i++)
        if (v[i]) idx[b * NKV + o++] = t * 4 + i;

    if (t == 1023) {
        cnt[b]  = sums[1023];
        cntp[b] = (sums[1023] + 127) & ~127;
    }
}

// ============================================================================
// gather kept q_x rows (by idx) and split to bf16 hi/lo; zero the pad rows.
// grid (NKV, BATCH), 128 threads; each thread handles 4 floats of one row.
// ============================================================================
__global__ void __launch_bounds__(128) gather_split_kernel(
    const float* __restrict__ qx, const int* __restrict__ idx,
    const int* __restrict__ cnt, const int* __restrict__ cntp,
    __nv_bfloat16* __restrict__ xh, __nv_bfloat16* __restrict__ xl)
{
    const int b = blockIdx.y;
    const int j = blockIdx.x;
    if (j >= cntp[b]) return;

    const size_t drow = ((size_t)b * NKV + j) * DIM;
    uint2* dh = (uint2*)(xh + drow) + threadIdx.x;
    uint2* dl = (uint2*)(xl + drow) + threadIdx.x;

    if (j < cnt[b]) {
        const int r = idx[b * NKV + j];
        float4 vv = *((const float4*)(qx + ((size_t)b * NKV + r) * DIM) + threadIdx.x);
        uint32_t h0, l0, h1, l1;
        pack_split(vv.x, vv.y, h0, l0);
        pack_split(vv.z, vv.w, h1, l1);
        *dh = make_uint2(h0, h1);
        *dl = make_uint2(l0, l1);
    } else {
        *dh = make_uint2(0u, 0u);
        *dl = make_uint2(0u, 0u);
    }
}

// ============================================================================
// elementwise fp32 -> (hi, lo) bf16 split
// ============================================================================
__global__ void __launch_bounds__(256) split_kernel(
    const float* __restrict__ in, __nv_bfloat16* __restrict__ h,
    __nv_bfloat16* __restrict__ l, int n4)
{
    int i = blockIdx.x * 256 + threadIdx.x;
    if (i >= n4) return;
    float4 v = ((const float4*)in)[i];
    uint32_t h0, l0, h1, l1;
    pack_split(v.x, v.y, h0, l0);
    pack_split(v.z, v.w, h1, l1);
    ((uint2*)h)[i] = make_uint2(h0, h1);
    ((uint2*)l)[i] = make_uint2(l0, l1);
}

__global__ void __launch_bounds__(256) split4_kernel(
    const float* __restrict__ w0, const float* __restrict__ w1,
    const float* __restrict__ w2, const float* __restrict__ w3,
    __nv_bfloat16* __restrict__ h0o, __nv_bfloat16* __restrict__ l0o,
    __nv_bfloat16* __restrict__ h1o, __nv_bfloat16* __restrict__ l1o,
    __nv_bfloat16* __restrict__ h2o, __nv_bfloat16* __restrict__ l2o,
    __nv_bfloat16* __restrict__ h3o, __nv_bfloat16* __restrict__ l3o,
    int n4)
{
    int i = blockIdx.x * 256 + threadIdx.x;
    if (i >= n4) return;
    const float* in = blockIdx.y == 0 ? w0 : blockIdx.y == 1 ? w1
                    : blockIdx.y == 2 ? w2 : w3;
    __nv_bfloat16* h = blockIdx.y == 0 ? h0o : blockIdx.y == 1 ? h1o
                     : blockIdx.y == 2 ? h2o : h3o;
    __nv_bfloat16* l = blockIdx.y == 0 ? l0o : blockIdx.y == 1 ? l1o
                     : blockIdx.y == 2 ? l2o : l3o;
    float4 v = ((const float4*)in)[i];
    uint32_t ha, la, hb, lb;
    pack_split(v.x, v.y, ha, la);
    pack_split(v.z, v.w, hb, lb);
    ((uint2*)h)[i] = make_uint2(ha, hb);
    ((uint2*)l)[i] = make_uint2(la, lb);
}

// ============================================================================
// bf16x3 GEMM NT, warp tile 64x64, ldmatrix fragments, tile early-exit and
// per-batch dynamic K:  C[M,N] = alpha * (Ah+Al)[M,K] @ (Bh+Bl)[N,K]^T
// ldA/ldB = element strides of A/B rows (may exceed K for compacted arrays).
// mlim/nlim: optional per-batch tile bounds (skip if m0/n0 >= lim[z]).
// kdyn: optional per-batch K (multiple of 32).
// ============================================================================
#define PAD2      40
#define ROW_B     (PAD2 * 2)               // 80 bytes per row
#define TILE_B    (128 * ROW_B)            // 10240
#define STAGE_B   (4 * TILE_B)             // 40960
#define GEMM_SMEM (2 * STAGE_B)            // 81920

__global__ void __launch_bounds__(128, 2) gemm_nt_split(
    const __nv_bfloat16* __restrict__ Ah, const __nv_bfloat16* __restrict__ Al,
    const __nv_bfloat16* __restrict__ Bh, const __nv_bfloat16* __restrict__ Bl,
    float* __restrict__ Cf,
    __nv_bfloat16* __restrict__ Ch, __nv_bfloat16* __restrict__ Cl,
    int M, int N, int K, int ldA, int ldB,
    size_t sA, size_t sB, size_t sC, float alpha,
    const int* __restrict__ mlim, const int* __restrict__ nlim,
    const int* __restrict__ kdyn)
{
    extern __shared__ __align__(16) char smem[];
    const uint32_t sbase = smem_u32(smem);

    const int m0 = blockIdx.y * 128;
    const int n0 = blockIdx.x * 128;
    if (mlim && m0 >= mlim[blockIdx.z]) return;
    if (nlim && n0 >= nlim[blockIdx.z]) return;
    if (kdyn) K = kdyn[blockIdx.z];

    const int t    = threadIdx.x;
    const int wid  = t >> 5;
    const int lane = t & 31;
    const int g    = lane >> 2;
    const int c    = lane & 3;
    const int warp_m = wid >> 1;
    const int warp_n = wid & 1;

    const uint32_t a_row = lane & 15;
    const uint32_t a_kh  = (lane >> 4) * 16;
    const uint32_t b_row = (lane & 7) + ((lane >> 4) << 3);
    const uint32_t b_kh  = ((lane >> 3) & 1) * 16;

    Ah += (size_t)blockIdx.z * sA;  Al += (size_t)blockIdx.z * sA;
    Bh += (size_t)blockIdx.z * sB;  Bl += (size_t)blockIdx.z * sB;

    auto load_tile = [&](int kt, int s) {
        const uint32_t st = sbase + (uint32_t)(s * STAGE_B);
        const int kb = kt * 32;
        #pragma unroll
        for (int ph = 0; ph < 4; ph++) {
            int idx = ph * 128 + t;
            int row = idx >> 2;
            int c4  = idx & 3;
            uint32_t so = (uint32_t)(row * ROW_B + c4 * 16);
            const size_t ga = (size_t)(m0 + row) * ldA + kb + c4 * 8;
            const size_t gb = (size_t)(n0 + row) * ldB + kb + c4 * 8;
            cp_async16(st + 0 * TILE_B + so, Ah + ga);
            cp_async16(st + 1 * TILE_B + so, Al + ga);
            cp_async16(st + 2 * TILE_B + so, Bh + gb);
            cp_async16(st + 3 * TILE_B + so, Bl + gb);
        }
        cp_commit();
    };

    float acc[4][8][4] = {};

    const int nkt = K >> 5;
    load_tile(0, 0);

    for (int kt = 0; kt < nkt; kt++) {
        const int s = kt & 1;
        if (kt + 1 < nkt) {
            load_tile(kt + 1, s ^ 1);
            cp_wait1();
        } else {
            cp_wait0();
        }
        __syncthreads();

        const uint32_t aB = sbase + s * STAGE_B + warp_m * 64 * ROW_B;
        const uint32_t bB = sbase + s * STAGE_B + 2 * TILE_B + warp_n * 64 * ROW_B;

        #pragma unroll
        for (int ks2 = 0; ks2 < 2; ks2++) {
            const uint32_t kso = ks2 * 32;

            uint32_t bh[8][2], bl[8][2];
            #pragma unroll
            for (int p = 0; p < 4; p++) {
                uint32_t addr = bB + (p * 16 + b_row) * ROW_B + kso + b_kh;
                ldsm_x4(bh[2*p][0], bh[2*p][1], bh[2*p+1][0], bh[2*p+1][1], addr);
                ldsm_x4(bl[2*p][0], bl[2*p][1], bl[2*p+1][0], bl[2*p+1][1],
                        addr + TILE_B);
            }

            #pragma unroll
            for (int mt = 0; mt < 4; mt++) {
                uint32_t addr = aB + (mt * 16 + a_row) * ROW_B + kso + a_kh;
                uint32_t ah[4], al[4];
                ldsm_x4(ah[0], ah[1], ah[2], ah[3], addr);
                ldsm_x4(al[0], al[1], al[2], al[3], addr + TILE_B);
                #pragma unroll
                for (int nt = 0; nt < 8; nt++) {
                    mma_bf16(acc[mt][nt], al, bh[nt]);
                    mma_bf16(acc[mt][nt], ah, bl[nt]);
                    mma_bf16(acc[mt][nt], ah, bh[nt]);
                }
            }
        }
        __syncthreads();
    }

    if (Cf) {
        Cf += (size_t)blockIdx.z * sC;
        #pragma unroll
        for (int mt = 0; mt < 4; mt++) {
            const int row = m0 + warp_m * 64 + mt * 16 + g;
            #pragma unroll
            for (int nt = 0; nt < 8; nt++) {
                const int col = n0 + warp_n * 64 + nt * 8 + 2 * c;
                *(float2*)(Cf + (size_t)row * N + col) =
                    make_float2(acc[mt][nt][0] * alpha, acc[mt][nt][1] * alpha);
                *(float2*)(Cf + (size_t)(row + 8) * N + col) =
                    make_float2(acc[mt][nt][2] * alpha, acc[mt][nt][3] * alpha);
            }
        }
    } else {
        Ch += (size_t)blockIdx.z * sC;
        Cl += (size_t)blockIdx.z * sC;
        #pragma unroll
        for (int mt = 0; mt < 4; mt++) {
            const int row = m0 + warp_m * 64 + mt * 16 + g;
            #pragma unroll
            for (int nt = 0; nt < 8; nt++) {
                const int col = n0 + warp_n * 64 + nt * 8 + 2 * c;
                uint32_t h, l;
                pack_split(acc[mt][nt][0] * alpha, acc[mt][nt][1] * alpha, h, l);
                *(uint32_t*)(Ch + (size_t)row * N + col) = h;
                *(uint32_t*)(Cl + (size_t)row * N + col) = l;
                pack_split(acc[mt][nt][2] * alpha, acc[mt][nt][3] * alpha, h, l);
                *(uint32_t*)(Ch + (size_t)(row + 8) * N + col) = h;
                *(uint32_t*)(Cl + (size_t)(row + 8) * N + col) = l;
            }
        }
    }
}

// ============================================================================
// softmax over compacted scores: row width cnt[b] (pad to cntp[b] with P=0).
// No mask bias needed: masked positions are exactly 0 in the reference too.
// ============================================================================
__global__ void __launch_bounds__(256) softmax_c_kernel(
    const float* __restrict__ attn, const int* __restrict__ cnt,
    const int* __restrict__ cntp,
    __nv_bfloat16* __restrict__ Ph, __nv_bfloat16* __restrict__ Pl)
{
    const int row = blockIdx.x;
    const int b   = row >> 10;             // NQ = 1024
    const int cn  = cnt[b];
    const int cp  = cntp[b];
    const float2* p = (const float2*)(attn + (size_t)row * NKV);

    float2 v[8];
    float mx = -3.0e38f;
    #pragma unroll
    for (int i = 0; i < 8; i++) {
        int j2 = threadIdx.x + i * 256;
        int j  = 2 * j2;
        float2 x = make_float2(-3.0e38f, -3.0e38f);
        if (j < cp) {
            x = p[j2];
            if (j     >= cn) x.x = -3.0e38f;
            if (j + 1 >= cn) x.y = -3.0e38f;
        }
        v[i] = x;
        mx = fmaxf(mx, fmaxf(x.x, x.y));
    }

    __shared__ float red[8];
    #pragma unroll
    for (int o = 16; o; o >>= 1) mx = fmaxf(mx, __shfl_xor_sync(0xffffffffu, mx, o));
    if ((threadIdx.x & 31) == 0) red[threadIdx.x >> 5] = mx;
    __syncthreads();
    float bm = red[0];
    #pragma unroll
    for (int w = 1; w < 8; w++) bm = fmaxf(bm, red[w]);
    __syncthreads();

    float sum = 0.0f;
    #pragma unroll
    for (int i = 0; i < 8; i++) {
        v[i].x = __expf(v[i].x - bm);
        v[i].y = __expf(v[i].y - bm);
        sum += v[i].x + v[i].y;
    }
    #pragma unroll
    for (int o = 16; o; o >>= 1) sum += __shfl_xor_sync(0xffffffffu, sum, o);
    if ((threadIdx.x & 31) == 0) red[threadIdx.x >> 5] = sum;
    __syncthreads();
    float ts = red[0];
    #pragma unroll
    for (int w = 1; w < 8; w++) ts += red[w];
    float inv = 1.0f / ts;

    #pragma unroll
    for (int i = 0; i < 8; i++) {
        int j2 = threadIdx.x + i * 256;
        int j  = 2 * j2;
        if (j < cp) {
            uint32_t h, l;
            pack_split(v[i].x * inv, v[i].y * inv, h, l);
            *(uint32_t*)(Ph + (size_t)row * NKV + j) = h;
            *(uint32_t*)(Pl + (size_t)row * NKV + j) = l;
        }
    }
}

// ============================================================================
// launch
// ============================================================================
extern "C" void kernel_launch(void* const* d_in, const int* in_sizes, int n_in,
                              void* d_out, int out_size)
{
    const float* prototype = (const float*)d_in[0];
    const float* q_x       = (const float*)d_in[1];
    const int*   mask      = (const int*)  d_in[2];
    const float* Wq        = (const float*)d_in[3];
    const float* Wk        = (const float*)d_in[4];
    const float* Wv        = (const float*)d_in[5];
    const float* Wproj     = (const float*)d_in[6];
    float* out = (float*)d_out;

    __nv_bfloat16 *ph, *pl, *xh, *xl, *wqh, *wql, *wkh, *wkl, *wvh, *wvl,
                  *wph, *wpl, *qh, *ql, *kh, *kl, *vth, *vtl, *aph, *apl, *oh, *ol;
    float* attn;
    int *idx, *cnt, *cntp;
    cudaGetSymbolAddress((void**)&ph,  s_ph);  cudaGetSymbolAddress((void**)&pl,  s_pl);
    cudaGetSymbolAddress((void**)&xh,  s_xh);  cudaGetSymbolAddress((void**)&xl,  s_xl);
    cudaGetSymbolAddress((void**)&wqh, s_wqh); cudaGetSymbolAddress((void**)&wql, s_wql);
    cudaGetSymbolAddress((void**)&wkh, s_wkh); cudaGetSymbolAddress((void**)&wkl, s_wkl);
    cudaGetSymbolAddress((void**)&wvh, s_wvh); cudaGetSymbolAddress((void**)&wvl, s_wvl);
    cudaGetSymbolAddress((void**)&wph, s_wph); cudaGetSymbolAddress((void**)&wpl, s_wpl);
    cudaGetSymbolAddress((void**)&qh,  s_qh);  cudaGetSymbolAddress((void**)&ql,  s_ql);
    cudaGetSymbolAddress((void**)&kh,  s_kh);  cudaGetSymbolAddress((void**)&kl,  s_kl);
    cudaGetSymbolAddress((void**)&vth, s_vth); cudaGetSymbolAddress((void**)&vtl, s_vtl);
    cudaGetSymbolAddress((void**)&aph, s_aph); cudaGetSymbolAddress((void**)&apl, s_apl);
    cudaGetSymbolAddress((void**)&oh,  s_oh);  cudaGetSymbolAddress((void**)&ol,  s_ol);
    cudaGetSymbolAddress((void**)&attn, g_attn);
    cudaGetSymbolAddress((void**)&idx,  g_idx);
    cudaGetSymbolAddress((void**)&cnt,  g_cnt);
    cudaGetSymbolAddress((void**)&cntp, g_cntp);

    cudaFuncSetAttribute(gemm_nt_split,
                         cudaFuncAttributeMaxDynamicSharedMemorySize, GEMM_SMEM);

    const float scale = 0.04419417382415922f;  // 1/sqrt(512)
    dim3 blk(128);

    // mask scan + gather/split of kept q_x rows
    mask_scan_kernel<<<BATCH, 1024>>>(mask, idx, cnt, cntp);
    gather_split_kernel<<<dim3(NKV, BATCH), 128>>>(q_x, idx, cnt, cntp, xh, xl);

    // splits of dense inputs
    split_kernel<<<(BATCH*NQ*DIM/4 + 255)/256, 256>>>(prototype, ph, pl, BATCH*NQ*DIM/4);
    split4_kernel<<<dim3((DIM*DIM/4 + 255)/256, 4), 256>>>(
        Wq, Wk, Wv, Wproj, wqh, wql, wkh, wkl, wvh, wvl, wph, wpl, DIM*DIM/4);

    // q = prototype @ Wq^T : M=8192, N=512, K=512
    gemm_nt_split<<<dim3(DIM/128, (BATCH*NQ)/128, 1), blk, GEMM_SMEM>>>(
        ph, pl, wqh, wql, nullptr, qh, ql,
        BATCH*NQ, DIM, DIM, DIM, DIM, 0, 0, 0, 1.0f,
        nullptr, nullptr, nullptr);

    // kc[b] = xc[b] @ Wk^T : per batch M=cntp[b] (<=NKV), N=512, K=512
    gemm_nt_split<<<dim3(DIM/128, NKV/128, BATCH), blk, GEMM_SMEM>>>(
        xh, xl, wkh, wkl, nullptr, kh, kl,
        NKV, DIM, DIM, DIM, DIM,
        (size_t)NKV*DIM, 0, (size_t)NKV*DIM, 1.0f,
        cntp, nullptr, nullptr);

    // vTc[b] = Wv @ xc[b]^T : per batch M=512, N=cntp[b], K=512
    gemm_nt_split<<<dim3(NKV/128, DIM/128, BATCH), blk, GEMM_SMEM>>>(
        wvh, wvl, xh, xl, nullptr, vth, vtl,
        DIM, NKV, DIM, DIM, DIM,
        0, (size_t)NKV*DIM, (size_t)DIM*NKV, 1.0f,
        nullptr, cntp, nullptr);

    // attn[b] = scale * q[b] @ kc[b]^T : M=1024, N=cntp[b], K=512
    gemm_nt_split<<<dim3(NKV/128, NQ/128, BATCH), blk, GEMM_SMEM>>>(
        qh, ql, kh, kl, attn, nullptr, nullptr,
        NQ, NKV, DIM, DIM, DIM,
        (size_t)NQ*DIM, (size_t)NKV*DIM, (size_t)NQ*NKV, scale,
        nullptr, cntp, nullptr);

    // softmax over compacted width -> split probs (0 in pad region)
    softmax_c_kernel<<<BATCH*NQ, 256>>>(attn, cnt, cntp, aph, apl);

    // x[b] = Pc[b] @ vTc[b]^T : M=1024, N=512, K=cntp[b]
    gemm_nt_split<<<dim3(DIM/128, NQ/128, BATCH), blk, GEMM_SMEM>>>(
        aph, apl, vth, vtl, nullptr, oh, ol,
        NQ, DIM, NKV, NKV, NKV,
        (size_t)NQ*NKV, (size_t)DIM*NKV, (size_t)NQ*DIM, 1.0f,
        nullptr, nullptr, cntp);

    // out = x @ Wproj^T : M=8192, N=512, K=512
    gemm_nt_split<<<dim3(DIM/128, (BATCH*NQ)/128, 1), blk, GEMM_SMEM>>>(
        oh, ol, wph, wpl, out, nullptr, nullptr,
        BATCH*NQ, DIM, DIM, DIM, DIM, 0, 0, 0, 1.0f,
        nullptr, nullptr, nullptr);
}